// round 8
// baseline (speedup 1.0000x reference)
#include <cuda_runtime.h>
#include <cuda_fp16.h>
#include <cstdint>

#define N_NODES 55296
#define N_EDGES 221184
#define NROWS   (2 * N_NODES)   /* B*N = 110592 */
#define EPC     256             /* edges per CTA */
#define NTILES  (N_EDGES / EPC) /* 864 */

typedef unsigned long long ull;

// ---------------- scratch (device globals; no allocation) ----------------
__device__ float  d_g [(size_t)N_EDGES * 32];     // relu(edge MLP hidden)
__device__ float  d_h [(size_t)NROWS * 32];       // hidden/node carry
__device__ float  d_agg[(size_t)NROWS * 32];      // scatter accumulator
__device__ __half d_BT[32 * 1056];                // BT[o][k*32+h]=ew2[k,h*32+o]; BT[o][1024+h]=eb2[h*32+o]

__device__ __forceinline__ float sigm(float x) { return 1.f / (1.f + __expf(-x)); }
__device__ __forceinline__ ull pack2(float lo, float hi) {
    ull r; asm("mov.b64 %0, {%1,%2};" : "=l"(r) : "f"(lo), "f"(hi)); return r;
}
__device__ __forceinline__ void unpack2(ull v, float& lo, float& hi) {
    asm("mov.b64 {%0,%1}, %2;" : "=f"(lo), "=f"(hi) : "l"(v));
}
__device__ __forceinline__ ull ffma2(ull a, ull b, ull c) {
    ull d; asm("fma.rn.f32x2 %0, %1, %2, %3;" : "=l"(d) : "l"(a), "l"(b), "l"(c)); return d;
}

// smem layout for msg kernel (bytes), EPC=256
#define BSTRIDE 1064     /* halves; 532 words = 20 mod 32 -> conflict-free */
#define XSTRIDE 40       /* halves; 20 words mod 32 -> conflict-free */
#define SM_B    0        /* 32 rows x 1064 halves = 68096 */
#define SM_X    68096    /* 2*256 rows x 40 halves = 40960 */
#define SM_G    109056   /* 256 rows x 40 halves = 20480 */
#define SM_SRC  129536   /* 1024 */
#define SM_DST  130560   /* 1024 */
#define SM_TOTAL 131584

// ---------------- h0: project node features + zero agg ----------------
__global__ void h0_kernel(const float* __restrict__ x,
                          const float* __restrict__ pw1, const float* __restrict__ pb1,
                          const float* __restrict__ pw2, const float* __restrict__ pb2) {
    __shared__ float w1s[1024], w2s[1024], b1s[32], b2s[32];
    int tid = threadIdx.x;
    for (int idx = tid; idx < 1024; idx += 256) { w1s[idx] = pw1[idx]; w2s[idx] = pw2[idx]; }
    if (tid < 32) { b1s[tid] = pb1[tid]; b2s[tid] = pb2[tid]; }
    __syncthreads();
    int row = blockIdx.x * 8 + (tid >> 5);
    int j = tid & 31;
    float xj = x[(size_t)row * 32 + j];
    float a = b1s[j];
#pragma unroll
    for (int i = 0; i < 32; i++) a = fmaf(__shfl_sync(0xffffffffu, xj, i), w1s[i * 32 + j], a);
    a = fmaxf(a, 0.f);
    float o = b2s[j];
#pragma unroll
    for (int i = 0; i < 32; i++) o = fmaf(__shfl_sync(0xffffffffu, a, i), w2s[i * 32 + j], o);
    d_h[(size_t)row * 32 + j] = o;
    d_agg[(size_t)row * 32 + j] = 0.f;
}

// ---------------- prep: g = relu(er@ew1+eb1)  AND  BT transpose (merged) ----------------
#define G_BLOCKS 27648   /* (N_EDGES*32)/256 */
__global__ void prep_kernel(const float* __restrict__ er,
                            const float* __restrict__ ew1, const float* __restrict__ eb1,
                            const float* __restrict__ ew2, const float* __restrict__ eb2) {
    int bid = blockIdx.x;
    if (bid < G_BLOCKS) {
        int tid = bid * 256 + threadIdx.x;
        int e = tid >> 5, j = tid & 31;
        float4 rv = __ldg((const float4*)er + e);
        float a = __ldg(eb1 + j);
        a = fmaf(rv.x, __ldg(ew1 + j),      a);
        a = fmaf(rv.y, __ldg(ew1 + 32 + j), a);
        a = fmaf(rv.z, __ldg(ew1 + 64 + j), a);
        a = fmaf(rv.w, __ldg(ew1 + 96 + j), a);
        d_g[tid] = fmaxf(a, 0.f);
    } else {
        int t = (bid - G_BLOCKS) * 256 + threadIdx.x;
        if (t >= 32 * 1056) return;
        int o = t / 1056, K = t % 1056;
        float v;
        if (K < 1024) {
            int k = K >> 5, h = K & 31;
            v = ew2[k * 1024 + h * 32 + o];
        } else {
            v = eb2[(K - 1024) * 32 + o];
        }
        d_BT[t] = __float2half_rn(v);
    }
}

// ---------------- fused msg: D = (g ox x) @ W2^T via mma.sync, red-scatter ----------------
__device__ __forceinline__ void mma_f16(float& d0, float& d1, float& d2, float& d3,
                                        uint32_t a0, uint32_t a1, uint32_t a2, uint32_t a3,
                                        uint32_t b0, uint32_t b1) {
    asm volatile("mma.sync.aligned.m16n8k16.row.col.f32.f16.f16.f32 "
                 "{%0,%1,%2,%3}, {%4,%5,%6,%7}, {%8,%9}, {%0,%1,%2,%3};"
                 : "+f"(d0), "+f"(d1), "+f"(d2), "+f"(d3)
                 : "r"(a0), "r"(a1), "r"(a2), "r"(a3), "r"(b0), "r"(b1));
}

__global__ void __launch_bounds__(256, 1) msg_fused(const int* __restrict__ esrc,
                                                    const int* __restrict__ edst) {
    extern __shared__ char smem[];
    __half* Bs = (__half*)(smem + SM_B);
    __half* xs = (__half*)(smem + SM_X);
    __half* gs = (__half*)(smem + SM_G);
    int* srcs = (int*)(smem + SM_SRC);
    int* dsts = (int*)(smem + SM_DST);

    int tid = threadIdx.x;
    int w = tid >> 5, l = tid & 31;
    int e0 = blockIdx.x * EPC;

    { srcs[tid] = esrc[e0 + tid]; dsts[tid] = edst[e0 + tid]; }
    __syncthreads();

    // stage B: 4224 uint4 (32 rows x 132 uint4) from d_BT into padded rows
    for (int idx = tid; idx < 4224; idx += 256) {
        int o = idx / 132, c8 = (idx - o * 132) * 8;
        *(uint4*)(Bs + o * BSTRIDE + c8) = ((const uint4*)d_BT)[idx];
    }
    // stage x (both batches, gathered via src) as fp16
#pragma unroll
    for (int it = 0; it < 8; it++) {
        int t = tid + it * 256;            // 2048 tasks: b, row, quarter(8 floats)
        int b = t >> 10, rq = t & 1023;
        int row = rq >> 2, qq = rq & 3;
        int src = srcs[row];
        const float4* p = (const float4*)(d_h + ((size_t)b * N_NODES + src) * 32 + qq * 8);
        float4 v0 = p[0], v1 = p[1];
        __half2 h0 = __floats2half2_rn(v0.x, v0.y), h1 = __floats2half2_rn(v0.z, v0.w);
        __half2 h2 = __floats2half2_rn(v1.x, v1.y), h3 = __floats2half2_rn(v1.z, v1.w);
        uint4 pk = { *(uint32_t*)&h0, *(uint32_t*)&h1, *(uint32_t*)&h2, *(uint32_t*)&h3 };
        *(uint4*)(xs + (b * 256 + row) * XSTRIDE + qq * 8) = pk;
    }
    // stage g as fp16
#pragma unroll
    for (int it = 0; it < 4; it++) {
        int t = tid + it * 256;            // 1024 tasks
        int row = t >> 2, qq = t & 3;
        const float4* p = (const float4*)(d_g + (size_t)(e0 + row) * 32 + qq * 8);
        float4 v0 = p[0], v1 = p[1];
        __half2 h0 = __floats2half2_rn(v0.x, v0.y), h1 = __floats2half2_rn(v0.z, v0.w);
        __half2 h2 = __floats2half2_rn(v1.x, v1.y), h3 = __floats2half2_rn(v1.z, v1.w);
        uint4 pk = { *(uint32_t*)&h0, *(uint32_t*)&h1, *(uint32_t*)&h2, *(uint32_t*)&h3 };
        *(uint4*)(gs + row * XSTRIDE + qq * 8) = pk;
    }
    __syncthreads();

    int q = l & 3, r0 = l >> 2, q2 = q * 2;
    int rowbase = w * 32;
    int row4[4] = { rowbase + r0, rowbase + r0 + 8, rowbase + r0 + 16, rowbase + r0 + 24 };

    // registerize x pairs for BOTH batches
    uint32_t xr[2][4][4];
#pragma unroll
    for (int b = 0; b < 2; b++)
#pragma unroll
        for (int i = 0; i < 4; i++) {
            const __half* xp = xs + (b * 256 + row4[i]) * XSTRIDE + q2;
#pragma unroll
            for (int p = 0; p < 4; p++) xr[b][i][p] = *(const uint32_t*)(xp + 8 * p);
        }

    float acc[2][2][4][4];
#pragma unroll
    for (int b = 0; b < 2; b++)
#pragma unroll
        for (int mt = 0; mt < 2; mt++)
#pragma unroll
            for (int nt = 0; nt < 4; nt++)
#pragma unroll
                for (int d = 0; d < 4; d++) acc[b][mt][nt][d] = 0.f;

    for (int kk = 0; kk < 33; kk++) {      // kk==32 -> bias block (A = x, no g)
        bool hasg = (kk < 32);
        __half2 g2[4];
        if (hasg) {
#pragma unroll
            for (int i = 0; i < 4; i++) g2[i] = __half2half2(gs[row4[i] * XSTRIDE + kk]);
        }
#pragma unroll
        for (int hh = 0; hh < 2; hh++) {
            int Kb = kk * 32 + hh * 16;
            uint32_t bf[4][2];
#pragma unroll
            for (int nt = 0; nt < 4; nt++) {
                const __half* bp = Bs + (nt * 8 + r0) * BSTRIDE + Kb + q2;
                bf[nt][0] = *(const uint32_t*)bp;
                bf[nt][1] = *(const uint32_t*)(bp + 8);
            }
#pragma unroll
            for (int b = 0; b < 2; b++) {
#pragma unroll
                for (int mt = 0; mt < 2; mt++) {
                    uint32_t a0 = xr[b][2 * mt][2 * hh],     a1 = xr[b][2 * mt + 1][2 * hh];
                    uint32_t a2 = xr[b][2 * mt][2 * hh + 1], a3 = xr[b][2 * mt + 1][2 * hh + 1];
                    if (hasg) {
                        __half2 gA = g2[2 * mt], gB = g2[2 * mt + 1];
                        __half2 t;
                        t = __hmul2(gA, *(__half2*)&a0); a0 = *(uint32_t*)&t;
                        t = __hmul2(gB, *(__half2*)&a1); a1 = *(uint32_t*)&t;
                        t = __hmul2(gA, *(__half2*)&a2); a2 = *(uint32_t*)&t;
                        t = __hmul2(gB, *(__half2*)&a3); a3 = *(uint32_t*)&t;
                    }
#pragma unroll
                    for (int nt = 0; nt < 4; nt++)
                        mma_f16(acc[b][mt][nt][0], acc[b][mt][nt][1], acc[b][mt][nt][2], acc[b][mt][nt][3],
                                a0, a1, a2, a3, bf[nt][0], bf[nt][1]);
                }
            }
        }
    }
    // scatter
#pragma unroll
    for (int b = 0; b < 2; b++)
#pragma unroll
        for (int mt = 0; mt < 2; mt++) {
            int dA = dsts[row4[2 * mt]], dB = dsts[row4[2 * mt + 1]];
            float* pA = d_agg + ((size_t)b * N_NODES + dA) * 32 + q2;
            float* pB = d_agg + ((size_t)b * N_NODES + dB) * 32 + q2;
#pragma unroll
            for (int nt = 0; nt < 4; nt++) {
                asm volatile("red.global.add.v2.f32 [%0], {%1,%2};"
                             :: "l"(pA + nt * 8), "f"(acc[b][mt][nt][0]), "f"(acc[b][mt][nt][1]) : "memory");
                asm volatile("red.global.add.v2.f32 [%0], {%1,%2};"
                             :: "l"(pB + nt * 8), "f"(acc[b][mt][nt][2]), "f"(acc[b][mt][nt][3]) : "memory");
            }
        }
}

// ---------------- GRU step: 64 rows/CTA, f32x2 row-pair math (also re-zeroes agg) ----------------
__global__ void gru_kernel(const float* __restrict__ conv_b,
                           const float* __restrict__ wih, const float* __restrict__ whh,
                           const float* __restrict__ bih, const float* __restrict__ bhh,
                           float* __restrict__ out, int last) {
    __shared__ float WihT[32 * 96], WhhT[32 * 96];   // [h][gate*32+j]
    __shared__ float bihs[96], bhhs[96], cbs[32];
    __shared__ float2 xs2[32][33], hs2[32][33];      // [feature][row-pair]
    int tid = threadIdx.x;
    for (int idx = tid; idx < 3072; idx += 256) {
        int j3 = idx >> 5, h = idx & 31;
        WihT[h * 96 + j3] = wih[idx];
        WhhT[h * 96 + j3] = whh[idx];
    }
    if (tid < 96) { bihs[tid] = bih[tid]; bhhs[tid] = bhh[tid]; }
    if (tid < 32) cbs[tid] = conv_b[tid];
    __syncthreads();
    int row0 = blockIdx.x * 64;
#pragma unroll
    for (int r = 0; r < 8; r++) {
        int idx = tid + r * 256;
        int rr = idx >> 5, c = idx & 31;
        size_t off = (size_t)(row0 + rr) * 32 + c;
        ((float*)&xs2[c][rr >> 1])[rr & 1] = fmaxf(d_agg[off] + cbs[c], 0.f);
        ((float*)&hs2[c][rr >> 1])[rr & 1] = d_h[off];
        d_agg[off] = 0.f;
    }
    __syncthreads();
    int w = tid >> 5, j = tid & 31;       // warp handles pairs w*4..w*4+3 (rows w*8..w*8+7)
    ull axr[4], axz[4], axn[4], ahr[4], ahz[4], ahn[4];
    {
        ull br = pack2(bihs[j], bihs[j]), bz = pack2(bihs[32 + j], bihs[32 + j]), bn = pack2(bihs[64 + j], bihs[64 + j]);
        ull cr = pack2(bhhs[j], bhhs[j]), cz = pack2(bhhs[32 + j], bhhs[32 + j]), cn = pack2(bhhs[64 + j], bhhs[64 + j]);
#pragma unroll
        for (int pr = 0; pr < 4; pr++) { axr[pr] = br; axz[pr] = bz; axn[pr] = bn; ahr[pr] = cr; ahz[pr] = cz; ahn[pr] = cn; }
    }
#pragma unroll 4
    for (int h = 0; h < 32; h++) {
        float wr = WihT[h * 96 + j], wz = WihT[h * 96 + 32 + j], wn = WihT[h * 96 + 64 + j];
        float vr = WhhT[h * 96 + j], vz = WhhT[h * 96 + 32 + j], vn = WhhT[h * 96 + 64 + j];
        ull wr2 = pack2(wr, wr), wz2 = pack2(wz, wz), wn2 = pack2(wn, wn);
        ull vr2 = pack2(vr, vr), vz2 = pack2(vz, vz), vn2 = pack2(vn, vn);
#pragma unroll
        for (int pr = 0; pr < 4; pr++) {
            ull xv = *(const ull*)&xs2[h][w * 4 + pr];    // broadcast LDS.64
            ull hv = *(const ull*)&hs2[h][w * 4 + pr];
            axr[pr] = ffma2(xv, wr2, axr[pr]);
            axz[pr] = ffma2(xv, wz2, axz[pr]);
            axn[pr] = ffma2(xv, wn2, axn[pr]);
            ahr[pr] = ffma2(hv, vr2, ahr[pr]);
            ahz[pr] = ffma2(hv, vz2, ahz[pr]);
            ahn[pr] = ffma2(hv, vn2, ahn[pr]);
        }
    }
    float* dst = last ? out : (float*)d_h;
#pragma unroll
    for (int pr = 0; pr < 4; pr++) {
        float xr0, xr1, xz0, xz1, xn0, xn1, hr0, hr1, hz0, hz1, hn0, hn1;
        unpack2(axr[pr], xr0, xr1); unpack2(axz[pr], xz0, xz1); unpack2(axn[pr], xn0, xn1);
        unpack2(ahr[pr], hr0, hr1); unpack2(ahz[pr], hz0, hz1); unpack2(ahn[pr], hn0, hn1);
        float hp0 = ((const float*)&hs2[j][w * 4 + pr])[0];
        float hp1 = ((const float*)&hs2[j][w * 4 + pr])[1];
        {
            float rg = sigm(xr0 + hr0), zg = sigm(xz0 + hz0);
            float ng = tanhf(fmaf(rg, hn0, xn0));
            dst[(size_t)(row0 + (w * 4 + pr) * 2) * 32 + j] = (1.f - zg) * ng + zg * hp0;
        }
        {
            float rg = sigm(xr1 + hr1), zg = sigm(xz1 + hz1);
            float ng = tanhf(fmaf(rg, hn1, xn1));
            dst[(size_t)(row0 + (w * 4 + pr) * 2 + 1) * 32 + j] = (1.f - zg) * ng + zg * hp1;
        }
    }
}

// ---------------- launch ----------------
extern "C" void kernel_launch(void* const* d_in, const int* in_sizes, int n_in,
                              void* d_out, int out_size) {
    const float* x     = (const float*)d_in[0];
    const float* er    = (const float*)d_in[1];
    const float* pw1   = (const float*)d_in[2];
    const float* pb1   = (const float*)d_in[3];
    const float* pw2   = (const float*)d_in[4];
    const float* pb2   = (const float*)d_in[5];
    const float* ew1   = (const float*)d_in[6];
    const float* eb1   = (const float*)d_in[7];
    const float* ew2   = (const float*)d_in[8];
    const float* eb2   = (const float*)d_in[9];
    const float* convb = (const float*)d_in[10];
    const float* wih   = (const float*)d_in[11];
    const float* whh   = (const float*)d_in[12];
    const float* bih   = (const float*)d_in[13];
    const float* bhh   = (const float*)d_in[14];
    const int*   esrc  = (const int*)d_in[15];
    const int*   edst  = (const int*)d_in[16];
    float* outp = (float*)d_out;

    cudaFuncSetAttribute(msg_fused, cudaFuncAttributeMaxDynamicSharedMemorySize, SM_TOTAL);

    h0_kernel<<<NROWS / 8, 256>>>(x, pw1, pb1, pw2, pb2);
    prep_kernel<<<G_BLOCKS + 132, 256>>>(er, ew1, eb1, ew2, eb2);
    for (int s = 0; s < 3; s++) {
        msg_fused<<<NTILES, 256, SM_TOTAL>>>(esrc, edst);
        gru_kernel<<<NROWS / 64, 256>>>(convb, wih, whh, bih, bhh, outp, s == 2 ? 1 : 0);
    }
}

// round 9
// speedup vs baseline: 1.0804x; 1.0804x over previous
#include <cuda_runtime.h>
#include <cuda_fp16.h>
#include <cstdint>

#define N_NODES 55296
#define N_EDGES 221184
#define NROWS   (2 * N_NODES)   /* B*N = 110592 */
#define EPC     256             /* edges per CTA */
#define NTILES  (N_EDGES / EPC) /* 864 */

// ---------------- scratch (device globals; no allocation) ----------------
__device__ float  d_g [(size_t)N_EDGES * 32];     // relu(edge MLP hidden)
__device__ float  d_h [(size_t)NROWS * 32];       // hidden/node carry
__device__ float  d_agg[(size_t)NROWS * 32];      // scatter accumulator
__device__ __half d_BT[32 * 1056];                // BT[o][k*32+h]=ew2[k,h*32+o]; BT[o][1024+h]=eb2[h*32+o]

__device__ __forceinline__ float sigm(float x) {
    return __fdividef(1.f, 1.f + __expf(-x));
}
__device__ __forceinline__ float fast_tanh(float x) {
    float t = __expf(2.f * x);
    return 1.f - __fdividef(2.f, t + 1.f);
}

// smem layout for msg kernel (bytes), EPC=256
#define BSTRIDE 1064     /* halves; 532 words = 20 mod 32 -> conflict-free */
#define XSTRIDE 40       /* halves; 20 words mod 32 -> conflict-free */
#define SM_B    0        /* 32 rows x 1064 halves = 68096 */
#define SM_X    68096    /* 2*256 rows x 40 halves = 40960 */
#define SM_G    109056   /* 256 rows x 40 halves = 20480 */
#define SM_SRC  129536   /* 1024 */
#define SM_DST  130560   /* 1024 */
#define SM_TOTAL 131584

// ---------------- h0: project node features + zero agg ----------------
__global__ void h0_kernel(const float* __restrict__ x,
                          const float* __restrict__ pw1, const float* __restrict__ pb1,
                          const float* __restrict__ pw2, const float* __restrict__ pb2) {
    __shared__ float w1s[1024], w2s[1024], b1s[32], b2s[32];
    int tid = threadIdx.x;
    for (int idx = tid; idx < 1024; idx += 256) { w1s[idx] = pw1[idx]; w2s[idx] = pw2[idx]; }
    if (tid < 32) { b1s[tid] = pb1[tid]; b2s[tid] = pb2[tid]; }
    __syncthreads();
    int row = blockIdx.x * 8 + (tid >> 5);
    int j = tid & 31;
    float xj = x[(size_t)row * 32 + j];
    float a = b1s[j];
#pragma unroll
    for (int i = 0; i < 32; i++) a = fmaf(__shfl_sync(0xffffffffu, xj, i), w1s[i * 32 + j], a);
    a = fmaxf(a, 0.f);
    float o = b2s[j];
#pragma unroll
    for (int i = 0; i < 32; i++) o = fmaf(__shfl_sync(0xffffffffu, a, i), w2s[i * 32 + j], o);
    d_h[(size_t)row * 32 + j] = o;
    d_agg[(size_t)row * 32 + j] = 0.f;
}

// ---------------- prep: g = relu(er@ew1+eb1)  AND  BT transpose (merged) ----------------
#define G_BLOCKS 27648   /* (N_EDGES*32)/256 */
__global__ void prep_kernel(const float* __restrict__ er,
                            const float* __restrict__ ew1, const float* __restrict__ eb1,
                            const float* __restrict__ ew2, const float* __restrict__ eb2) {
    int bid = blockIdx.x;
    if (bid < G_BLOCKS) {
        int tid = bid * 256 + threadIdx.x;
        int e = tid >> 5, j = tid & 31;
        float4 rv = __ldg((const float4*)er + e);
        float a = __ldg(eb1 + j);
        a = fmaf(rv.x, __ldg(ew1 + j),      a);
        a = fmaf(rv.y, __ldg(ew1 + 32 + j), a);
        a = fmaf(rv.z, __ldg(ew1 + 64 + j), a);
        a = fmaf(rv.w, __ldg(ew1 + 96 + j), a);
        d_g[tid] = fmaxf(a, 0.f);
    } else {
        int t = (bid - G_BLOCKS) * 256 + threadIdx.x;
        if (t >= 32 * 1056) return;
        int o = t / 1056, K = t % 1056;
        float v;
        if (K < 1024) {
            int k = K >> 5, h = K & 31;
            v = ew2[k * 1024 + h * 32 + o];
        } else {
            v = eb2[(K - 1024) * 32 + o];
        }
        d_BT[t] = __float2half_rn(v);
    }
}

// ---------------- fused msg: D = (g ox x) @ W2^T via mma.sync, red-scatter ----------------
__device__ __forceinline__ void mma_f16(float& d0, float& d1, float& d2, float& d3,
                                        uint32_t a0, uint32_t a1, uint32_t a2, uint32_t a3,
                                        uint32_t b0, uint32_t b1) {
    asm volatile("mma.sync.aligned.m16n8k16.row.col.f32.f16.f16.f32 "
                 "{%0,%1,%2,%3}, {%4,%5,%6,%7}, {%8,%9}, {%0,%1,%2,%3};"
                 : "+f"(d0), "+f"(d1), "+f"(d2), "+f"(d3)
                 : "r"(a0), "r"(a1), "r"(a2), "r"(a3), "r"(b0), "r"(b1));
}

__global__ void __launch_bounds__(256, 1) msg_fused(const int* __restrict__ esrc,
                                                    const int* __restrict__ edst) {
    extern __shared__ char smem[];
    __half* Bs = (__half*)(smem + SM_B);
    __half* xs = (__half*)(smem + SM_X);
    __half* gs = (__half*)(smem + SM_G);
    int* srcs = (int*)(smem + SM_SRC);
    int* dsts = (int*)(smem + SM_DST);

    int tid = threadIdx.x;
    int w = tid >> 5, l = tid & 31;
    int e0 = blockIdx.x * EPC;

    { srcs[tid] = esrc[e0 + tid]; dsts[tid] = edst[e0 + tid]; }
    __syncthreads();

    // stage B: 4224 uint4 (32 rows x 132 uint4) from d_BT into padded rows
    for (int idx = tid; idx < 4224; idx += 256) {
        int o = idx / 132, c8 = (idx - o * 132) * 8;
        *(uint4*)(Bs + o * BSTRIDE + c8) = ((const uint4*)d_BT)[idx];
    }
    // stage x (both batches, gathered via src) as fp16
#pragma unroll
    for (int it = 0; it < 8; it++) {
        int t = tid + it * 256;            // 2048 tasks: b, row, quarter(8 floats)
        int b = t >> 10, rq = t & 1023;
        int row = rq >> 2, qq = rq & 3;
        int src = srcs[row];
        const float4* p = (const float4*)(d_h + ((size_t)b * N_NODES + src) * 32 + qq * 8);
        float4 v0 = p[0], v1 = p[1];
        __half2 h0 = __floats2half2_rn(v0.x, v0.y), h1 = __floats2half2_rn(v0.z, v0.w);
        __half2 h2 = __floats2half2_rn(v1.x, v1.y), h3 = __floats2half2_rn(v1.z, v1.w);
        uint4 pk = { *(uint32_t*)&h0, *(uint32_t*)&h1, *(uint32_t*)&h2, *(uint32_t*)&h3 };
        *(uint4*)(xs + (b * 256 + row) * XSTRIDE + qq * 8) = pk;
    }
    // stage g as fp16
#pragma unroll
    for (int it = 0; it < 4; it++) {
        int t = tid + it * 256;            // 1024 tasks
        int row = t >> 2, qq = t & 3;
        const float4* p = (const float4*)(d_g + (size_t)(e0 + row) * 32 + qq * 8);
        float4 v0 = p[0], v1 = p[1];
        __half2 h0 = __floats2half2_rn(v0.x, v0.y), h1 = __floats2half2_rn(v0.z, v0.w);
        __half2 h2 = __floats2half2_rn(v1.x, v1.y), h3 = __floats2half2_rn(v1.z, v1.w);
        uint4 pk = { *(uint32_t*)&h0, *(uint32_t*)&h1, *(uint32_t*)&h2, *(uint32_t*)&h3 };
        *(uint4*)(gs + row * XSTRIDE + qq * 8) = pk;
    }
    __syncthreads();

    int q = l & 3, r0 = l >> 2, q2 = q * 2;
    int rowbase = w * 32;
    int row4[4] = { rowbase + r0, rowbase + r0 + 8, rowbase + r0 + 16, rowbase + r0 + 24 };

    // registerize x pairs for BOTH batches
    uint32_t xr[2][4][4];
#pragma unroll
    for (int b = 0; b < 2; b++)
#pragma unroll
        for (int i = 0; i < 4; i++) {
            const __half* xp = xs + (b * 256 + row4[i]) * XSTRIDE + q2;
#pragma unroll
            for (int p = 0; p < 4; p++) xr[b][i][p] = *(const uint32_t*)(xp + 8 * p);
        }

    float acc[2][2][4][4];
#pragma unroll
    for (int b = 0; b < 2; b++)
#pragma unroll
        for (int mt = 0; mt < 2; mt++)
#pragma unroll
            for (int nt = 0; nt < 4; nt++)
#pragma unroll
                for (int d = 0; d < 4; d++) acc[b][mt][nt][d] = 0.f;

    for (int kk = 0; kk < 33; kk++) {      // kk==32 -> bias block (A = x, no g)
        bool hasg = (kk < 32);
        __half2 g2[4];
        if (hasg) {
#pragma unroll
            for (int i = 0; i < 4; i++) g2[i] = __half2half2(gs[row4[i] * XSTRIDE + kk]);
        }
#pragma unroll
        for (int hh = 0; hh < 2; hh++) {
            int Kb = kk * 32 + hh * 16;
            uint32_t bf[4][2];
#pragma unroll
            for (int nt = 0; nt < 4; nt++) {
                const __half* bp = Bs + (nt * 8 + r0) * BSTRIDE + Kb + q2;
                bf[nt][0] = *(const uint32_t*)bp;
                bf[nt][1] = *(const uint32_t*)(bp + 8);
            }
#pragma unroll
            for (int b = 0; b < 2; b++) {
#pragma unroll
                for (int mt = 0; mt < 2; mt++) {
                    uint32_t a0 = xr[b][2 * mt][2 * hh],     a1 = xr[b][2 * mt + 1][2 * hh];
                    uint32_t a2 = xr[b][2 * mt][2 * hh + 1], a3 = xr[b][2 * mt + 1][2 * hh + 1];
                    if (hasg) {
                        __half2 gA = g2[2 * mt], gB = g2[2 * mt + 1];
                        __half2 t;
                        t = __hmul2(gA, *(__half2*)&a0); a0 = *(uint32_t*)&t;
                        t = __hmul2(gB, *(__half2*)&a1); a1 = *(uint32_t*)&t;
                        t = __hmul2(gA, *(__half2*)&a2); a2 = *(uint32_t*)&t;
                        t = __hmul2(gB, *(__half2*)&a3); a3 = *(uint32_t*)&t;
                    }
#pragma unroll
                    for (int nt = 0; nt < 4; nt++)
                        mma_f16(acc[b][mt][nt][0], acc[b][mt][nt][1], acc[b][mt][nt][2], acc[b][mt][nt][3],
                                a0, a1, a2, a3, bf[nt][0], bf[nt][1]);
                }
            }
        }
    }
    // scatter
#pragma unroll
    for (int b = 0; b < 2; b++)
#pragma unroll
        for (int mt = 0; mt < 2; mt++) {
            int dA = dsts[row4[2 * mt]], dB = dsts[row4[2 * mt + 1]];
            float* pA = d_agg + ((size_t)b * N_NODES + dA) * 32 + q2;
            float* pB = d_agg + ((size_t)b * N_NODES + dB) * 32 + q2;
#pragma unroll
            for (int nt = 0; nt < 4; nt++) {
                asm volatile("red.global.add.v2.f32 [%0], {%1,%2};"
                             :: "l"(pA + nt * 8), "f"(acc[b][mt][nt][0]), "f"(acc[b][mt][nt][1]) : "memory");
                asm volatile("red.global.add.v2.f32 [%0], {%1,%2};"
                             :: "l"(pB + nt * 8), "f"(acc[b][mt][nt][2]), "f"(acc[b][mt][nt][3]) : "memory");
            }
        }
}

// ---------------- GRU step: 128 rows/CTA, scalar FFMA, padded transpose (re-zeroes agg) ----------------
#define WSTR 97   /* padded weight row stride (words): conflict-free STS and LDS */
__global__ void __launch_bounds__(256, 3) gru_kernel(
                           const float* __restrict__ conv_b,
                           const float* __restrict__ wih, const float* __restrict__ whh,
                           const float* __restrict__ bih, const float* __restrict__ bhh,
                           float* __restrict__ out, int last) {
    __shared__ float WihT[32 * WSTR], WhhT[32 * WSTR];   // [h][gate*32+j], stride 97
    __shared__ float bihs[96], bhhs[96], cbs[32];
    __shared__ float xs[128][33], hs2[128][33];
    int tid = threadIdx.x;
    for (int idx = tid; idx < 3072; idx += 256) {
        int j3 = idx >> 5, h = idx & 31;    // lanes: h varies -> stride 97 -> conflict-free
        WihT[h * WSTR + j3] = wih[idx];
        WhhT[h * WSTR + j3] = whh[idx];
    }
    if (tid < 96) { bihs[tid] = bih[tid]; bhhs[tid] = bhh[tid]; }
    if (tid < 32) cbs[tid] = conv_b[tid];
    __syncthreads();
    int row0 = blockIdx.x * 128;
#pragma unroll
    for (int r = 0; r < 16; r++) {
        int idx = tid + r * 256;
        int rr = idx >> 5, c = idx & 31;
        size_t off = (size_t)(row0 + rr) * 32 + c;
        xs[rr][c] = fmaxf(d_agg[off] + cbs[c], 0.f);
        hs2[rr][c] = d_h[off];
        d_agg[off] = 0.f;
    }
    __syncthreads();
    int w = tid >> 5, j = tid & 31;
    float* dst = last ? out : (float*)d_h;

#pragma unroll
    for (int half = 0; half < 2; half++) {
        int rbase = half * 64 + w * 8;      // this warp's 8 rows for this pass
        float gxr[8], gxz[8], gxn[8], ghr[8], ghz[8], ghn[8];
#pragma unroll
        for (int rr = 0; rr < 8; rr++) {
            gxr[rr] = bihs[j]; gxz[rr] = bihs[32 + j]; gxn[rr] = bihs[64 + j];
            ghr[rr] = bhhs[j]; ghz[rr] = bhhs[32 + j]; ghn[rr] = bhhs[64 + j];
        }
#pragma unroll 2
        for (int h = 0; h < 32; h++) {
            float wr = WihT[h * WSTR + j], wz = WihT[h * WSTR + 32 + j], wn = WihT[h * WSTR + 64 + j];
            float vr = WhhT[h * WSTR + j], vz = WhhT[h * WSTR + 32 + j], vn = WhhT[h * WSTR + 64 + j];
#pragma unroll
            for (int rr = 0; rr < 8; rr++) {
                float xb = xs[rbase + rr][h], hb = hs2[rbase + rr][h];
                gxr[rr] = fmaf(xb, wr, gxr[rr]); gxz[rr] = fmaf(xb, wz, gxz[rr]); gxn[rr] = fmaf(xb, wn, gxn[rr]);
                ghr[rr] = fmaf(hb, vr, ghr[rr]); ghz[rr] = fmaf(hb, vz, ghz[rr]); ghn[rr] = fmaf(hb, vn, ghn[rr]);
            }
        }
#pragma unroll
        for (int rr = 0; rr < 8; rr++) {
            float rg = sigm(gxr[rr] + ghr[rr]);
            float zg = sigm(gxz[rr] + ghz[rr]);
            float ng = fast_tanh(fmaf(rg, ghn[rr], gxn[rr]));
            float ho = hs2[rbase + rr][j];
            dst[(size_t)(row0 + rbase + rr) * 32 + j] = (1.f - zg) * ng + zg * ho;
        }
    }
}

// ---------------- launch ----------------
extern "C" void kernel_launch(void* const* d_in, const int* in_sizes, int n_in,
                              void* d_out, int out_size) {
    const float* x     = (const float*)d_in[0];
    const float* er    = (const float*)d_in[1];
    const float* pw1   = (const float*)d_in[2];
    const float* pb1   = (const float*)d_in[3];
    const float* pw2   = (const float*)d_in[4];
    const float* pb2   = (const float*)d_in[5];
    const float* ew1   = (const float*)d_in[6];
    const float* eb1   = (const float*)d_in[7];
    const float* ew2   = (const float*)d_in[8];
    const float* eb2   = (const float*)d_in[9];
    const float* convb = (const float*)d_in[10];
    const float* wih   = (const float*)d_in[11];
    const float* whh   = (const float*)d_in[12];
    const float* bih   = (const float*)d_in[13];
    const float* bhh   = (const float*)d_in[14];
    const int*   esrc  = (const int*)d_in[15];
    const int*   edst  = (const int*)d_in[16];
    float* outp = (float*)d_out;

    cudaFuncSetAttribute(msg_fused, cudaFuncAttributeMaxDynamicSharedMemorySize, SM_TOTAL);

    h0_kernel<<<NROWS / 8, 256>>>(x, pw1, pb1, pw2, pb2);
    prep_kernel<<<G_BLOCKS + 132, 256>>>(er, ew1, eb1, ew2, eb2);
    for (int s = 0; s < 3; s++) {
        msg_fused<<<NTILES, 256, SM_TOTAL>>>(esrc, edst);
        gru_kernel<<<NROWS / 128, 256>>>(convb, wih, whh, bih, bhh, outp, s == 2 ? 1 : 0);
    }
}